// round 1
// baseline (speedup 1.0000x reference)
#include <cuda_runtime.h>
#include <math.h>

#define NTOK 2048
#define CDIM 1024
#define NHEADS 16
#define HD 64
#define NCAM 2
#define NPER 1024

// ---------------- scratch (device globals; no allocations allowed) ----------------
static __device__ float g_qkv[(size_t)NTOK * 3 * CDIM];          // 24 MB
static __device__ float g_q[(size_t)NHEADS * NTOK * HD];         // 8 MB
static __device__ float g_k[(size_t)NHEADS * NTOK * HD];
static __device__ float g_v[(size_t)NHEADS * NTOK * HD];
static __device__ float g_S[(size_t)NHEADS * NTOK * NTOK];       // 256 MB
static __device__ float g_oh[(size_t)NHEADS * NTOK * HD];
static __device__ float g_y[(size_t)NTOK * CDIM];
static __device__ float g_P[NCAM * 16];
static __device__ float g_Pinv[NCAM * 16];

// ---------------- camera matrices: P = Kn @ ext, Pinv = inv(P) ----------------
__global__ void setup_mats(const float* __restrict__ ext, const float* __restrict__ Ks) {
    int c = threadIdx.x;
    if (c >= NCAM) return;
    const float sx = 2.0f / 448.0f, sy = 2.0f / 448.0f;
    float fx = Ks[c * 9 + 0], cx = Ks[c * 9 + 2];
    float fy = Ks[c * 9 + 4], cy = Ks[c * 9 + 5];
    float Kn[4][4] = {};
    Kn[0][0] = fx * sx; Kn[0][2] = cx * sx - 1.0f;
    Kn[1][1] = fy * sy; Kn[1][2] = cy * sy - 1.0f;
    Kn[2][2] = 1.0f;    Kn[3][3] = 1.0f;
    float P[4][4];
    for (int i = 0; i < 4; i++)
        for (int j = 0; j < 4; j++) {
            float s = 0.f;
            for (int k = 0; k < 4; k++) s += Kn[i][k] * ext[c * 16 + k * 4 + j];
            P[i][j] = s;
            g_P[c * 16 + i * 4 + j] = s;
        }
    // Gauss-Jordan with partial pivoting
    float M[4][8];
    for (int i = 0; i < 4; i++)
        for (int j = 0; j < 4; j++) { M[i][j] = P[i][j]; M[i][4 + j] = (i == j) ? 1.f : 0.f; }
    for (int col = 0; col < 4; col++) {
        int piv = col;
        for (int r = col + 1; r < 4; r++)
            if (fabsf(M[r][col]) > fabsf(M[piv][col])) piv = r;
        if (piv != col)
            for (int j = 0; j < 8; j++) { float t = M[col][j]; M[col][j] = M[piv][j]; M[piv][j] = t; }
        float inv = 1.0f / M[col][col];
        for (int j = 0; j < 8; j++) M[col][j] *= inv;
        for (int r = 0; r < 4; r++) if (r != col) {
            float f = M[r][col];
            for (int j = 0; j < 8; j++) M[r][j] -= f * M[col][j];
        }
    }
    for (int i = 0; i < 4; i++)
        for (int j = 0; j < 4; j++) g_Pinv[c * 16 + i * 4 + j] = M[i][4 + j];
}

// ---------------- GEMM NT: C[i,j] = alpha * sum_k A[i,k]*B[j,k] (+bias[j]) ----------------
// BM=BN=64, BK=16, 256 threads, 4x4 microtile. Batched via blockIdx.z strides.
__global__ __launch_bounds__(256) void gemm_nt(
    const float* __restrict__ A, const float* __restrict__ B, float* __restrict__ C,
    int M, int N, int K, float alpha, const float* __restrict__ bias,
    size_t sA, size_t sB, size_t sC)
{
    A += (size_t)blockIdx.z * sA;
    B += (size_t)blockIdx.z * sB;
    C += (size_t)blockIdx.z * sC;
    __shared__ float As[16][64];
    __shared__ float Bs[16][64];
    const int tid = threadIdx.x;
    const int tx = tid & 15, ty = tid >> 4;
    const int row0 = blockIdx.y * 64;
    const int col0 = blockIdx.x * 64;
    const int lr = tid >> 2;           // 0..63
    const int lk = (tid & 3) << 2;     // 0,4,8,12
    float acc[4][4] = {};
    for (int kt = 0; kt < K; kt += 16) {
        float4 av = *(const float4*)(A + (size_t)(row0 + lr) * K + kt + lk);
        float4 bv = *(const float4*)(B + (size_t)(col0 + lr) * K + kt + lk);
        As[lk + 0][lr] = av.x; As[lk + 1][lr] = av.y; As[lk + 2][lr] = av.z; As[lk + 3][lr] = av.w;
        Bs[lk + 0][lr] = bv.x; Bs[lk + 1][lr] = bv.y; Bs[lk + 2][lr] = bv.z; Bs[lk + 3][lr] = bv.w;
        __syncthreads();
        #pragma unroll
        for (int kk = 0; kk < 16; kk++) {
            float4 a4 = *(const float4*)&As[kk][ty << 2];
            float4 b4 = *(const float4*)&Bs[kk][tx << 2];
            float a[4] = {a4.x, a4.y, a4.z, a4.w};
            float b[4] = {b4.x, b4.y, b4.z, b4.w};
            #pragma unroll
            for (int i = 0; i < 4; i++)
                #pragma unroll
                for (int j = 0; j < 4; j++)
                    acc[i][j] += a[i] * b[j];
        }
        __syncthreads();
    }
    const int c0 = col0 + (tx << 2);
    float b0 = 0, b1 = 0, b2 = 0, b3 = 0;
    if (bias) { b0 = bias[c0]; b1 = bias[c0 + 1]; b2 = bias[c0 + 2]; b3 = bias[c0 + 3]; }
    #pragma unroll
    for (int i = 0; i < 4; i++) {
        int r = row0 + (ty << 2) + i;
        float4 o;
        o.x = alpha * acc[i][0] + b0;
        o.y = alpha * acc[i][1] + b1;
        o.z = alpha * acc[i][2] + b2;
        o.w = alpha * acc[i][3] + b3;
        *(float4*)(C + (size_t)r * N + c0) = o;
    }
}

// ---------------- GEMM NN: C[i,j] = sum_k A[i,k]*B[k,j] ----------------
__global__ __launch_bounds__(256) void gemm_nn(
    const float* __restrict__ A, const float* __restrict__ B, float* __restrict__ C,
    int M, int N, int K,
    size_t sA, size_t sB, size_t sC)
{
    A += (size_t)blockIdx.z * sA;
    B += (size_t)blockIdx.z * sB;
    C += (size_t)blockIdx.z * sC;
    __shared__ float As[16][64];
    __shared__ float Bs[16][64];
    const int tid = threadIdx.x;
    const int tx = tid & 15, ty = tid >> 4;
    const int row0 = blockIdx.y * 64;
    const int col0 = blockIdx.x * 64;
    const int lr = tid >> 2;
    const int lk = (tid & 3) << 2;
    const int bk = tid >> 4;            // 0..15
    const int bc = (tid & 15) << 2;     // 0..60
    float acc[4][4] = {};
    for (int kt = 0; kt < K; kt += 16) {
        float4 av = *(const float4*)(A + (size_t)(row0 + lr) * K + kt + lk);
        As[lk + 0][lr] = av.x; As[lk + 1][lr] = av.y; As[lk + 2][lr] = av.z; As[lk + 3][lr] = av.w;
        float4 bv = *(const float4*)(B + (size_t)(kt + bk) * N + col0 + bc);
        *(float4*)&Bs[bk][bc] = bv;
        __syncthreads();
        #pragma unroll
        for (int kk = 0; kk < 16; kk++) {
            float4 a4 = *(const float4*)&As[kk][ty << 2];
            float4 b4 = *(const float4*)&Bs[kk][tx << 2];
            float a[4] = {a4.x, a4.y, a4.z, a4.w};
            float b[4] = {b4.x, b4.y, b4.z, b4.w};
            #pragma unroll
            for (int i = 0; i < 4; i++)
                #pragma unroll
                for (int j = 0; j < 4; j++)
                    acc[i][j] += a[i] * b[j];
        }
        __syncthreads();
    }
    const int c0 = col0 + (tx << 2);
    #pragma unroll
    for (int i = 0; i < 4; i++) {
        int r = row0 + (ty << 2) + i;
        float4 o = {acc[i][0], acc[i][1], acc[i][2], acc[i][3]};
        *(float4*)(C + (size_t)r * N + c0) = o;
    }
}

// ---------------- q/k/v transform: projective group matmul + RoPE ----------------
__global__ __launch_bounds__(64) void qkv_transform() {
    int nh = blockIdx.x;
    int n = nh >> 4;
    int h = nh & 15;
    int d = threadIdx.x;
    __shared__ float sq[64], sk[64], sv[64];
    const float* base = g_qkv + (size_t)n * 3072 + h * 64;
    sq[d] = base[d];
    sk[d] = base[1024 + d];
    sv[d] = base[2048 + d];
    __syncthreads();
    int cam = n / NPER;
    int p = n % NPER;
    float px = (float)(p & 31), py = (float)(p >> 5);
    float oq, ok, ov;
    if (d < 32) {
        int g = d & ~3, i = d & 3;
        const float* P  = g_P + cam * 16;
        const float* Pi = g_Pinv + cam * 16;
        oq = ok = ov = 0.f;
        #pragma unroll
        for (int j = 0; j < 4; j++) {
            oq += Pi[j * 4 + i] * sq[g + j];   // Mq = Pinv^T
            float pij = P[i * 4 + j];          // Mk = P
            ok += pij * sk[g + j];
            ov += pij * sv[g + j];
        }
    } else {
        int r = d - 32, pair = r >> 1, part = r & 1;
        float fr = powf(100.f, -(float)(pair & 7) * 0.125f);
        float ang = ((pair < 8) ? px : py) * fr;
        float cc = cosf(ang), ss = sinf(ang);
        int ia = 32 + (pair << 1), ib = ia + 1;
        if (part == 0) { oq = sq[ia] * cc - sq[ib] * ss; ok = sk[ia] * cc - sk[ib] * ss; ov = sv[ia] * cc - sv[ib] * ss; }
        else           { oq = sq[ia] * ss + sq[ib] * cc; ok = sk[ia] * ss + sk[ib] * cc; ov = sv[ia] * ss + sv[ib] * cc; }
    }
    size_t idx = ((size_t)h * NTOK + n) * HD + d;
    g_q[idx] = oq; g_k[idx] = ok; g_v[idx] = ov;
}

// ---------------- output transform: Mo = Pinv, rope sign = -1 ----------------
__global__ __launch_bounds__(64) void out_transform() {
    int nh = blockIdx.x;
    int n = nh >> 4;
    int h = nh & 15;
    int d = threadIdx.x;
    __shared__ float so[64];
    so[d] = g_oh[((size_t)h * NTOK + n) * HD + d];
    __syncthreads();
    int cam = n / NPER;
    int p = n % NPER;
    float px = (float)(p & 31), py = (float)(p >> 5);
    float o;
    if (d < 32) {
        int g = d & ~3, i = d & 3;
        const float* Pi = g_Pinv + cam * 16;
        o = 0.f;
        #pragma unroll
        for (int j = 0; j < 4; j++) o += Pi[i * 4 + j] * so[g + j];
    } else {
        int r = d - 32, pair = r >> 1, part = r & 1;
        float fr = powf(100.f, -(float)(pair & 7) * 0.125f);
        float ang = ((pair < 8) ? px : py) * fr;
        float cc = cosf(ang), ss = sinf(ang);
        int ia = 32 + (pair << 1), ib = ia + 1;
        if (part == 0) o =  so[ia] * cc + so[ib] * ss;   // s = -sin
        else           o = -so[ia] * ss + so[ib] * cc;
    }
    g_y[(size_t)n * CDIM + h * 64 + d] = o;
}

// ---------------- row softmax (2048 elems/row, values held in registers) ----------------
__global__ __launch_bounds__(256) void softmax_rows(float* __restrict__ S) {
    float* p = S + (size_t)blockIdx.x * NTOK;
    int t = threadIdx.x;
    float v[8];
    #pragma unroll
    for (int i = 0; i < 8; i++) v[i] = p[t + (i << 8)];
    float m = v[0];
    #pragma unroll
    for (int i = 1; i < 8; i++) m = fmaxf(m, v[i]);
    __shared__ float redm[8];
    #pragma unroll
    for (int o = 16; o; o >>= 1) m = fmaxf(m, __shfl_xor_sync(0xffffffffu, m, o));
    if ((t & 31) == 0) redm[t >> 5] = m;
    __syncthreads();
    m = redm[0];
    #pragma unroll
    for (int i = 1; i < 8; i++) m = fmaxf(m, redm[i]);
    float sum = 0.f;
    #pragma unroll
    for (int i = 0; i < 8; i++) { v[i] = __expf(v[i] - m); sum += v[i]; }
    __shared__ float reds[8];
    #pragma unroll
    for (int o = 16; o; o >>= 1) sum += __shfl_xor_sync(0xffffffffu, sum, o);
    if ((t & 31) == 0) reds[t >> 5] = sum;
    __syncthreads();
    sum = reds[0];
    #pragma unroll
    for (int i = 1; i < 8; i++) sum += reds[i];
    float inv = 1.0f / sum;
    #pragma unroll
    for (int i = 0; i < 8; i++) p[t + (i << 8)] = v[i] * inv;
}

// ---------------- launch ----------------
extern "C" void kernel_launch(void* const* d_in, const int* in_sizes, int n_in,
                              void* d_out, int out_size) {
    const float* x      = (const float*)d_in[0];
    const float* ext    = (const float*)d_in[1];
    const float* Kmat   = (const float*)d_in[2];
    const float* qkv_w  = (const float*)d_in[3];
    const float* proj_w = (const float*)d_in[4];
    const float* proj_b = (const float*)d_in[5];
    float* out = (float*)d_out;

    void *p_qkv, *p_q, *p_k, *p_v, *p_S, *p_oh, *p_y;
    cudaGetSymbolAddress(&p_qkv, g_qkv);
    cudaGetSymbolAddress(&p_q, g_q);
    cudaGetSymbolAddress(&p_k, g_k);
    cudaGetSymbolAddress(&p_v, g_v);
    cudaGetSymbolAddress(&p_S, g_S);
    cudaGetSymbolAddress(&p_oh, g_oh);
    cudaGetSymbolAddress(&p_y, g_y);

    setup_mats<<<1, 32>>>(ext, Kmat);

    // QKV: [2048,3072] = x[2048,1024] @ qkv_w[3072,1024]^T
    gemm_nt<<<dim3(3072 / 64, 2048 / 64), 256>>>(
        x, qkv_w, (float*)p_qkv, NTOK, 3072, CDIM, 1.0f, nullptr, 0, 0, 0);

    qkv_transform<<<NTOK * NHEADS, 64>>>();

    // S[h] = 0.125 * Q[h] @ K[h]^T   (M=N=2048, K=64, batched over 16 heads)
    gemm_nt<<<dim3(32, 32, NHEADS), 256>>>(
        (const float*)p_q, (const float*)p_k, (float*)p_S,
        NTOK, NTOK, HD, 0.125f, nullptr,
        (size_t)NTOK * HD, (size_t)NTOK * HD, (size_t)NTOK * NTOK);

    softmax_rows<<<NHEADS * NTOK, 256>>>((float*)p_S);

    // O[h] = S[h] @ V[h]   (M=2048, N=64, K=2048)
    gemm_nn<<<dim3(1, 32, NHEADS), 256>>>(
        (const float*)p_S, (const float*)p_v, (float*)p_oh,
        NTOK, HD, NTOK,
        (size_t)NTOK * NTOK, (size_t)NTOK * HD, (size_t)NTOK * HD);

    out_transform<<<NTOK * NHEADS, 64>>>();

    // final: out = y @ proj_w^T + proj_b
    gemm_nt<<<dim3(CDIM / 64, NTOK / 64), 256>>>(
        (const float*)p_y, proj_w, out, NTOK, CDIM, CDIM, 1.0f, proj_b, 0, 0, 0);
}

// round 3
// speedup vs baseline: 1.4186x; 1.4186x over previous
#include <cuda_runtime.h>
#include <math.h>

#define NTOK 2048
#define CDIM 1024
#define NHEADS 16
#define HD 64
#define NCAM 2
#define NPER 1024
#define LDT 36

// ---------------- scratch ----------------
static __device__ float g_qkv[(size_t)NTOK * 3 * CDIM];
static __device__ float g_q[(size_t)NHEADS * NTOK * HD];
static __device__ float g_k[(size_t)NHEADS * NTOK * HD];
static __device__ float g_v[(size_t)NHEADS * NTOK * HD];
static __device__ float g_S[(size_t)NHEADS * NTOK * NTOK];
static __device__ float g_oh[(size_t)NHEADS * NTOK * HD];
static __device__ float g_y[(size_t)NTOK * CDIM];
static __device__ float g_P[NCAM * 16];
static __device__ float g_Pinv[NCAM * 16];

// ---------------- helpers ----------------
__device__ __forceinline__ float f2tf32(float x) {
    unsigned u;
    asm("cvt.rna.tf32.f32 %0, %1;" : "=r"(u) : "f"(x));
    return __uint_as_float(u);
}
__device__ __forceinline__ void mma_tf32(float* d, const unsigned* a, const unsigned* b) {
    asm volatile(
        "mma.sync.aligned.m16n8k8.row.col.f32.tf32.tf32.f32 "
        "{%0,%1,%2,%3}, {%4,%5,%6,%7}, {%8,%9}, {%0,%1,%2,%3};\n"
        : "+f"(d[0]), "+f"(d[1]), "+f"(d[2]), "+f"(d[3])
        : "r"(a[0]), "r"(a[1]), "r"(a[2]), "r"(a[3]), "r"(b[0]), "r"(b[1]));
}

// ---------------- camera matrices ----------------
__global__ void setup_mats(const float* __restrict__ ext, const float* __restrict__ Ks) {
    int c = threadIdx.x;
    if (c >= NCAM) return;
    const float sx = 2.0f / 448.0f, sy = 2.0f / 448.0f;
    float fx = Ks[c * 9 + 0], cx = Ks[c * 9 + 2];
    float fy = Ks[c * 9 + 4], cy = Ks[c * 9 + 5];
    float Kn[4][4] = {};
    Kn[0][0] = fx * sx; Kn[0][2] = cx * sx - 1.0f;
    Kn[1][1] = fy * sy; Kn[1][2] = cy * sy - 1.0f;
    Kn[2][2] = 1.0f;    Kn[3][3] = 1.0f;
    float P[4][4];
    for (int i = 0; i < 4; i++)
        for (int j = 0; j < 4; j++) {
            float s = 0.f;
            for (int k = 0; k < 4; k++) s += Kn[i][k] * ext[c * 16 + k * 4 + j];
            P[i][j] = s;
            g_P[c * 16 + i * 4 + j] = s;
        }
    float M[4][8];
    for (int i = 0; i < 4; i++)
        for (int j = 0; j < 4; j++) { M[i][j] = P[i][j]; M[i][4 + j] = (i == j) ? 1.f : 0.f; }
    for (int col = 0; col < 4; col++) {
        int piv = col;
        for (int r = col + 1; r < 4; r++)
            if (fabsf(M[r][col]) > fabsf(M[piv][col])) piv = r;
        if (piv != col)
            for (int j = 0; j < 8; j++) { float t = M[col][j]; M[col][j] = M[piv][j]; M[piv][j] = t; }
        float inv = 1.0f / M[col][col];
        for (int j = 0; j < 8; j++) M[col][j] *= inv;
        for (int r = 0; r < 4; r++) if (r != col) {
            float f = M[r][col];
            for (int j = 0; j < 8; j++) M[r][j] -= f * M[col][j];
        }
    }
    for (int i = 0; i < 4; i++)
        for (int j = 0; j < 4; j++) g_Pinv[c * 16 + i * 4 + j] = M[i][4 + j];
}

// ---------------- TF32x3 GEMM NT: C = alpha * A[M,K] @ B[N,K]^T (+bias) ----------------
// BM=128, BN=128, BK=32. 8 warps in 2(m) x 4(n), warp tile 64x32.
// dynamic smem: Ah, Al, Bh, Bl each [128][LDT] floats.
__global__ __launch_bounds__(256) void gemm_nt_tf32(
    const float* __restrict__ A, const float* __restrict__ B, float* __restrict__ C,
    int M, int N, int K, float alpha, const float* __restrict__ bias,
    size_t sA, size_t sB, size_t sC)
{
    A += (size_t)blockIdx.z * sA;
    B += (size_t)blockIdx.z * sB;
    C += (size_t)blockIdx.z * sC;
    extern __shared__ float sm[];
    float* Ah = sm;
    float* Al = Ah + 128 * LDT;
    float* Bh = Al + 128 * LDT;
    float* Bl = Bh + 128 * LDT;
    const int tid = threadIdx.x;
    const int lane = tid & 31, warp = tid >> 5;
    const int g = lane >> 2, t = lane & 3;
    const int wm = (warp >> 2) * 64, wn = (warp & 3) * 32;
    const int row0 = blockIdx.y * 128;
    const int col0 = blockIdx.x * 128;
    const int lr = tid >> 3;            // 0..31
    const int lc4 = (tid & 7) * 4;      // 0..28
    float acc[4][4][4];
    #pragma unroll
    for (int i = 0; i < 4; i++)
        #pragma unroll
        for (int j = 0; j < 4; j++)
            #pragma unroll
            for (int e = 0; e < 4; e++) acc[i][j][e] = 0.f;

    for (int kt = 0; kt < K; kt += 32) {
        #pragma unroll
        for (int it = 0; it < 4; it++) {
            int r = lr + it * 32;
            float4 av = *(const float4*)(A + (size_t)(row0 + r) * K + kt + lc4);
            float4 bv = *(const float4*)(B + (size_t)(col0 + r) * K + kt + lc4);
            float4 ah = {f2tf32(av.x), f2tf32(av.y), f2tf32(av.z), f2tf32(av.w)};
            float4 al = {f2tf32(av.x - ah.x), f2tf32(av.y - ah.y), f2tf32(av.z - ah.z), f2tf32(av.w - ah.w)};
            float4 bh = {f2tf32(bv.x), f2tf32(bv.y), f2tf32(bv.z), f2tf32(bv.w)};
            float4 bl = {f2tf32(bv.x - bh.x), f2tf32(bv.y - bh.y), f2tf32(bv.z - bh.z), f2tf32(bv.w - bh.w)};
            *(float4*)&Ah[r * LDT + lc4] = ah;
            *(float4*)&Al[r * LDT + lc4] = al;
            *(float4*)&Bh[r * LDT + lc4] = bh;
            *(float4*)&Bl[r * LDT + lc4] = bl;
        }
        __syncthreads();
        #pragma unroll
        for (int kk = 0; kk < 4; kk++) {
            const int kc = kk * 8;
            // B fragments: b0 = (k=t, n=g), b1 = (k=t+4, n=g)
            unsigned bh_[4][2], bl_[4][2];
            #pragma unroll
            for (int nt = 0; nt < 4; nt++) {
                int nrow = (wn + nt * 8 + g) * LDT + kc + t;
                bh_[nt][0] = __float_as_uint(Bh[nrow]);
                bh_[nt][1] = __float_as_uint(Bh[nrow + 4]);
                bl_[nt][0] = __float_as_uint(Bl[nrow]);
                bl_[nt][1] = __float_as_uint(Bl[nrow + 4]);
            }
            #pragma unroll
            for (int mt = 0; mt < 4; mt++) {
                // A fragments: a0=(g,t) a1=(g+8,t) a2=(g,t+4) a3=(g+8,t+4)
                int r0 = (wm + mt * 16 + g) * LDT + kc + t;
                int r1 = (wm + mt * 16 + g + 8) * LDT + kc + t;
                unsigned ah_[4] = {__float_as_uint(Ah[r0]), __float_as_uint(Ah[r1]),
                                   __float_as_uint(Ah[r0 + 4]), __float_as_uint(Ah[r1 + 4])};
                unsigned al_[4] = {__float_as_uint(Al[r0]), __float_as_uint(Al[r1]),
                                   __float_as_uint(Al[r0 + 4]), __float_as_uint(Al[r1 + 4])};
                #pragma unroll
                for (int nt = 0; nt < 4; nt++) {
                    mma_tf32(acc[mt][nt], ah_, bh_[nt]);
                    mma_tf32(acc[mt][nt], ah_, bl_[nt]);
                    mma_tf32(acc[mt][nt], al_, bh_[nt]);
                }
            }
        }
        __syncthreads();
    }
    #pragma unroll
    for (int mt = 0; mt < 4; mt++) {
        int r = row0 + wm + mt * 16 + g;
        #pragma unroll
        for (int nt = 0; nt < 4; nt++) {
            int c = col0 + wn + nt * 8 + 2 * t;
            float b0 = 0.f, b1 = 0.f;
            if (bias) { b0 = bias[c]; b1 = bias[c + 1]; }
            float2 o0 = {alpha * acc[mt][nt][0] + b0, alpha * acc[mt][nt][1] + b1};
            float2 o1 = {alpha * acc[mt][nt][2] + b0, alpha * acc[mt][nt][3] + b1};
            *(float2*)(C + (size_t)r * N + c) = o0;
            *(float2*)(C + (size_t)(r + 8) * N + c) = o1;
        }
    }
}

// ---------------- TF32x3 GEMM PV: O[M,64] = S[M,K] @ V[K,64] ----------------
// BM=128, BN=64, BK=32. 8 warps in 4(m) x 2(n), warp tile 32x32.
__global__ __launch_bounds__(256) void gemm_pv_tf32(
    const float* __restrict__ A, const float* __restrict__ B, float* __restrict__ C,
    int M, int K, size_t sA, size_t sB, size_t sC)
{
    A += (size_t)blockIdx.z * sA;
    B += (size_t)blockIdx.z * sB;
    C += (size_t)blockIdx.z * sC;
    extern __shared__ float sm[];
    float* Ah = sm;
    float* Al = Ah + 128 * LDT;
    float* Bh = Al + 128 * LDT;
    float* Bl = Bh + 64 * LDT;
    const int tid = threadIdx.x;
    const int lane = tid & 31, warp = tid >> 5;
    const int g = lane >> 2, t = lane & 3;
    const int wm = (warp >> 1) * 32, wn = (warp & 1) * 32;
    const int row0 = blockIdx.y * 128;
    const int lr = tid >> 3;
    const int lc4 = (tid & 7) * 4;
    float acc[2][4][4];
    #pragma unroll
    for (int i = 0; i < 2; i++)
        #pragma unroll
        for (int j = 0; j < 4; j++)
            #pragma unroll
            for (int e = 0; e < 4; e++) acc[i][j][e] = 0.f;

    for (int kt = 0; kt < K; kt += 32) {
        #pragma unroll
        for (int it = 0; it < 4; it++) {
            int r = lr + it * 32;
            float4 av = *(const float4*)(A + (size_t)(row0 + r) * K + kt + lc4);
            float4 ah = {f2tf32(av.x), f2tf32(av.y), f2tf32(av.z), f2tf32(av.w)};
            float4 al = {f2tf32(av.x - ah.x), f2tf32(av.y - ah.y), f2tf32(av.z - ah.z), f2tf32(av.w - ah.w)};
            *(float4*)&Ah[r * LDT + lc4] = ah;
            *(float4*)&Al[r * LDT + lc4] = al;
        }
        // B: [K,64] row-major -> Bs[n][k] transposed store
        #pragma unroll
        for (int it = 0; it < 2; it++) {
            int k = tid & 31;
            int n4 = ((tid >> 5) + it * 8) * 4;
            float4 bv = *(const float4*)(B + (size_t)(kt + k) * 64 + n4);
            float h0 = f2tf32(bv.x), h1 = f2tf32(bv.y), h2 = f2tf32(bv.z), h3 = f2tf32(bv.w);
            Bh[(n4 + 0) * LDT + k] = h0;
            Bh[(n4 + 1) * LDT + k] = h1;
            Bh[(n4 + 2) * LDT + k] = h2;
            Bh[(n4 + 3) * LDT + k] = h3;
            Bl[(n4 + 0) * LDT + k] = f2tf32(bv.x - h0);
            Bl[(n4 + 1) * LDT + k] = f2tf32(bv.y - h1);
            Bl[(n4 + 2) * LDT + k] = f2tf32(bv.z - h2);
            Bl[(n4 + 3) * LDT + k] = f2tf32(bv.w - h3);
        }
        __syncthreads();
        #pragma unroll
        for (int kk = 0; kk < 4; kk++) {
            const int kc = kk * 8;
            unsigned bh_[4][2], bl_[4][2];
            #pragma unroll
            for (int nt = 0; nt < 4; nt++) {
                int nrow = (wn + nt * 8 + g) * LDT + kc + t;
                bh_[nt][0] = __float_as_uint(Bh[nrow]);
                bh_[nt][1] = __float_as_uint(Bh[nrow + 4]);
                bl_[nt][0] = __float_as_uint(Bl[nrow]);
                bl_[nt][1] = __float_as_uint(Bl[nrow + 4]);
            }
            #pragma unroll
            for (int mt = 0; mt < 2; mt++) {
                int r0 = (wm + mt * 16 + g) * LDT + kc + t;
                int r1 = (wm + mt * 16 + g + 8) * LDT + kc + t;
                unsigned ah_[4] = {__float_as_uint(Ah[r0]), __float_as_uint(Ah[r1]),
                                   __float_as_uint(Ah[r0 + 4]), __float_as_uint(Ah[r1 + 4])};
                unsigned al_[4] = {__float_as_uint(Al[r0]), __float_as_uint(Al[r1]),
                                   __float_as_uint(Al[r0 + 4]), __float_as_uint(Al[r1 + 4])};
                #pragma unroll
                for (int nt = 0; nt < 4; nt++) {
                    mma_tf32(acc[mt][nt], ah_, bh_[nt]);
                    mma_tf32(acc[mt][nt], ah_, bl_[nt]);
                    mma_tf32(acc[mt][nt], al_, bh_[nt]);
                }
            }
        }
        __syncthreads();
    }
    #pragma unroll
    for (int mt = 0; mt < 2; mt++) {
        int r = row0 + wm + mt * 16 + g;
        #pragma unroll
        for (int nt = 0; nt < 4; nt++) {
            int c = wn + nt * 8 + 2 * t;
            float2 o0 = {acc[mt][nt][0], acc[mt][nt][1]};
            float2 o1 = {acc[mt][nt][2], acc[mt][nt][3]};
            *(float2*)(C + (size_t)r * 64 + c) = o0;
            *(float2*)(C + (size_t)(r + 8) * 64 + c) = o1;
        }
    }
}

// ---------------- q/k/v transform ----------------
__global__ __launch_bounds__(64) void qkv_transform() {
    int nh = blockIdx.x;
    int n = nh >> 4;
    int h = nh & 15;
    int d = threadIdx.x;
    __shared__ float sq[64], sk[64], sv[64];
    const float* base = g_qkv + (size_t)n * 3072 + h * 64;
    sq[d] = base[d];
    sk[d] = base[1024 + d];
    sv[d] = base[2048 + d];
    __syncthreads();
    int cam = n / NPER;
    int p = n % NPER;
    float px = (float)(p & 31), py = (float)(p >> 5);
    float oq, ok, ov;
    if (d < 32) {
        int gg = d & ~3, i = d & 3;
        const float* P  = g_P + cam * 16;
        const float* Pi = g_Pinv + cam * 16;
        oq = ok = ov = 0.f;
        #pragma unroll
        for (int j = 0; j < 4; j++) {
            oq += Pi[j * 4 + i] * sq[gg + j];
            float pij = P[i * 4 + j];
            ok += pij * sk[gg + j];
            ov += pij * sv[gg + j];
        }
    } else {
        int r = d - 32, pair = r >> 1, part = r & 1;
        float fr = powf(100.f, -(float)(pair & 7) * 0.125f);
        float ang = ((pair < 8) ? px : py) * fr;
        float cc = cosf(ang), ss = sinf(ang);
        int ia = 32 + (pair << 1), ib = ia + 1;
        if (part == 0) { oq = sq[ia] * cc - sq[ib] * ss; ok = sk[ia] * cc - sk[ib] * ss; ov = sv[ia] * cc - sv[ib] * ss; }
        else           { oq = sq[ia] * ss + sq[ib] * cc; ok = sk[ia] * ss + sk[ib] * cc; ov = sv[ia] * ss + sv[ib] * cc; }
    }
    size_t idx = ((size_t)h * NTOK + n) * HD + d;
    g_q[idx] = oq; g_k[idx] = ok; g_v[idx] = ov;
}

// ---------------- output transform ----------------
__global__ __launch_bounds__(64) void out_transform() {
    int nh = blockIdx.x;
    int n = nh >> 4;
    int h = nh & 15;
    int d = threadIdx.x;
    __shared__ float so[64];
    so[d] = g_oh[((size_t)h * NTOK + n) * HD + d];
    __syncthreads();
    int cam = n / NPER;
    int p = n % NPER;
    float px = (float)(p & 31), py = (float)(p >> 5);
    float o;
    if (d < 32) {
        int gg = d & ~3, i = d & 3;
        const float* Pi = g_Pinv + cam * 16;
        o = 0.f;
        #pragma unroll
        for (int j = 0; j < 4; j++) o += Pi[i * 4 + j] * so[gg + j];
    } else {
        int r = d - 32, pair = r >> 1, part = r & 1;
        float fr = powf(100.f, -(float)(pair & 7) * 0.125f);
        float ang = ((pair < 8) ? px : py) * fr;
        float cc = cosf(ang), ss = sinf(ang);
        int ia = 32 + (pair << 1), ib = ia + 1;
        if (part == 0) o =  so[ia] * cc + so[ib] * ss;
        else           o = -so[ia] * ss + so[ib] * cc;
    }
    g_y[(size_t)n * CDIM + h * 64 + d] = o;
}

// ---------------- row softmax ----------------
__global__ __launch_bounds__(256) void softmax_rows(float* __restrict__ S) {
    float* p = S + (size_t)blockIdx.x * NTOK;
    int t = threadIdx.x;
    float v[8];
    #pragma unroll
    for (int i = 0; i < 8; i++) v[i] = p[t + (i << 8)];
    float m = v[0];
    #pragma unroll
    for (int i = 1; i < 8; i++) m = fmaxf(m, v[i]);
    __shared__ float redm[8];
    #pragma unroll
    for (int o = 16; o; o >>= 1) m = fmaxf(m, __shfl_xor_sync(0xffffffffu, m, o));
    if ((t & 31) == 0) redm[t >> 5] = m;
    __syncthreads();
    m = redm[0];
    #pragma unroll
    for (int i = 1; i < 8; i++) m = fmaxf(m, redm[i]);
    float sum = 0.f;
    #pragma unroll
    for (int i = 0; i < 8; i++) { v[i] = __expf(v[i] - m); sum += v[i]; }
    __shared__ float reds[8];
    #pragma unroll
    for (int o = 16; o; o >>= 1) sum += __shfl_xor_sync(0xffffffffu, sum, o);
    if ((t & 31) == 0) reds[t >> 5] = sum;
    __syncthreads();
    sum = reds[0];
    #pragma unroll
    for (int i = 1; i < 8; i++) sum += reds[i];
    float inv = 1.0f / sum;
    #pragma unroll
    for (int i = 0; i < 8; i++) p[t + (i << 8)] = v[i] * inv;
}

// ---------------- launch ----------------
extern "C" void kernel_launch(void* const* d_in, const int* in_sizes, int n_in,
                              void* d_out, int out_size) {
    const float* x      = (const float*)d_in[0];
    const float* ext    = (const float*)d_in[1];
    const float* Kmat   = (const float*)d_in[2];
    const float* qkv_w  = (const float*)d_in[3];
    const float* proj_w = (const float*)d_in[4];
    const float* proj_b = (const float*)d_in[5];
    float* out = (float*)d_out;

    const int SM_NT = 4 * 128 * LDT * 4;                 // 73728 B
    const int SM_PV = (2 * 128 * LDT + 2 * 64 * LDT) * 4; // 55296 B
    static bool attr_done = false;
    if (!attr_done) {
        cudaFuncSetAttribute(gemm_nt_tf32, cudaFuncAttributeMaxDynamicSharedMemorySize, SM_NT);
        cudaFuncSetAttribute(gemm_pv_tf32, cudaFuncAttributeMaxDynamicSharedMemorySize, SM_PV);
        attr_done = true;
    }

    void *p_qkv, *p_q, *p_k, *p_v, *p_S, *p_oh, *p_y;
    cudaGetSymbolAddress(&p_qkv, g_qkv);
    cudaGetSymbolAddress(&p_q, g_q);
    cudaGetSymbolAddress(&p_k, g_k);
    cudaGetSymbolAddress(&p_v, g_v);
    cudaGetSymbolAddress(&p_S, g_S);
    cudaGetSymbolAddress(&p_oh, g_oh);
    cudaGetSymbolAddress(&p_y, g_y);

    setup_mats<<<1, 32>>>(ext, Kmat);

    // QKV: [2048,3072] = x @ qkv_w^T
    gemm_nt_tf32<<<dim3(3072 / 128, 2048 / 128), 256, SM_NT>>>(
        x, qkv_w, (float*)p_qkv, NTOK, 3072, CDIM, 1.0f, nullptr, 0, 0, 0);

    qkv_transform<<<NTOK * NHEADS, 64>>>();

    // S[h] = 0.125 * Q[h] @ K[h]^T
    gemm_nt_tf32<<<dim3(16, 16, NHEADS), 256, SM_NT>>>(
        (const float*)p_q, (const float*)p_k, (float*)p_S,
        NTOK, NTOK, HD, 0.125f, nullptr,
        (size_t)NTOK * HD, (size_t)NTOK * HD, (size_t)NTOK * NTOK);

    softmax_rows<<<NHEADS * NTOK, 256>>>((float*)p_S);

    // O[h] = P[h] @ V[h]
    gemm_pv_tf32<<<dim3(1, 16, NHEADS), 256, SM_PV>>>(
        (const float*)p_S, (const float*)p_v, (float*)p_oh,
        NTOK, NTOK,
        (size_t)NTOK * NTOK, (size_t)NTOK * HD, (size_t)NTOK * HD);

    out_transform<<<NTOK * NHEADS, 64>>>();

    // out = y @ proj_w^T + proj_b
    gemm_nt_tf32<<<dim3(1024 / 128, 2048 / 128), 256, SM_NT>>>(
        (const float*)p_y, proj_w, out, NTOK, CDIM, CDIM, 1.0f, proj_b, 0, 0, 0);
}

// round 4
// speedup vs baseline: 1.5515x; 1.0937x over previous
#include <cuda_runtime.h>
#include <math.h>

#define NTOK 2048
#define CDIM 1024
#define NHEADS 16
#define HD 64
#define NCAM 2
#define NPER 1024
#define LDT 36

// ---------------- scratch ----------------
static __device__ float g_qkv[(size_t)NTOK * 3 * CDIM];
static __device__ float g_q[(size_t)NHEADS * NTOK * HD];
static __device__ float g_k[(size_t)NHEADS * NTOK * HD];
static __device__ float g_v[(size_t)NHEADS * NTOK * HD];
static __device__ float g_oh[(size_t)NHEADS * NTOK * HD];
static __device__ float g_y[(size_t)NTOK * CDIM];
static __device__ float g_P[NCAM * 16];
static __device__ float g_Pinv[NCAM * 16];

// ---------------- helpers ----------------
__device__ __forceinline__ float f2tf32(float x) {
    unsigned u;
    asm("cvt.rna.tf32.f32 %0, %1;" : "=r"(u) : "f"(x));
    return __uint_as_float(u);
}
__device__ __forceinline__ void mma_tf32(float* d, const unsigned* a, const unsigned* b) {
    asm volatile(
        "mma.sync.aligned.m16n8k8.row.col.f32.tf32.tf32.f32 "
        "{%0,%1,%2,%3}, {%4,%5,%6,%7}, {%8,%9}, {%0,%1,%2,%3};\n"
        : "+f"(d[0]), "+f"(d[1]), "+f"(d[2]), "+f"(d[3])
        : "r"(a[0]), "r"(a[1]), "r"(a[2]), "r"(a[3]), "r"(b[0]), "r"(b[1]));
}

// ---------------- camera matrices ----------------
__global__ void setup_mats(const float* __restrict__ ext, const float* __restrict__ Ks) {
    int c = threadIdx.x;
    if (c >= NCAM) return;
    const float sx = 2.0f / 448.0f, sy = 2.0f / 448.0f;
    float fx = Ks[c * 9 + 0], cx = Ks[c * 9 + 2];
    float fy = Ks[c * 9 + 4], cy = Ks[c * 9 + 5];
    float Kn[4][4] = {};
    Kn[0][0] = fx * sx; Kn[0][2] = cx * sx - 1.0f;
    Kn[1][1] = fy * sy; Kn[1][2] = cy * sy - 1.0f;
    Kn[2][2] = 1.0f;    Kn[3][3] = 1.0f;
    float P[4][4];
    for (int i = 0; i < 4; i++)
        for (int j = 0; j < 4; j++) {
            float s = 0.f;
            for (int k = 0; k < 4; k++) s += Kn[i][k] * ext[c * 16 + k * 4 + j];
            P[i][j] = s;
            g_P[c * 16 + i * 4 + j] = s;
        }
    float M[4][8];
    for (int i = 0; i < 4; i++)
        for (int j = 0; j < 4; j++) { M[i][j] = P[i][j]; M[i][4 + j] = (i == j) ? 1.f : 0.f; }
    for (int col = 0; col < 4; col++) {
        int piv = col;
        for (int r = col + 1; r < 4; r++)
            if (fabsf(M[r][col]) > fabsf(M[piv][col])) piv = r;
        if (piv != col)
            for (int j = 0; j < 8; j++) { float t = M[col][j]; M[col][j] = M[piv][j]; M[piv][j] = t; }
        float inv = 1.0f / M[col][col];
        for (int j = 0; j < 8; j++) M[col][j] *= inv;
        for (int r = 0; r < 4; r++) if (r != col) {
            float f = M[r][col];
            for (int j = 0; j < 8; j++) M[r][j] -= f * M[col][j];
        }
    }
    for (int i = 0; i < 4; i++)
        for (int j = 0; j < 4; j++) g_Pinv[c * 16 + i * 4 + j] = M[i][4 + j];
}

// ---------------- TF32x3 GEMM NT (QKV / proj) ----------------
__global__ __launch_bounds__(256) void gemm_nt_tf32(
    const float* __restrict__ A, const float* __restrict__ B, float* __restrict__ C,
    int M, int N, int K, float alpha, const float* __restrict__ bias,
    size_t sA, size_t sB, size_t sC)
{
    A += (size_t)blockIdx.z * sA;
    B += (size_t)blockIdx.z * sB;
    C += (size_t)blockIdx.z * sC;
    extern __shared__ float sm[];
    float* Ah = sm;
    float* Al = Ah + 128 * LDT;
    float* Bh = Al + 128 * LDT;
    float* Bl = Bh + 128 * LDT;
    const int tid = threadIdx.x;
    const int lane = tid & 31, warp = tid >> 5;
    const int g = lane >> 2, t = lane & 3;
    const int wm = (warp >> 2) * 64, wn = (warp & 3) * 32;
    const int row0 = blockIdx.y * 128;
    const int col0 = blockIdx.x * 128;
    const int lr = tid >> 3;
    const int lc4 = (tid & 7) * 4;
    float acc[4][4][4];
    #pragma unroll
    for (int i = 0; i < 4; i++)
        #pragma unroll
        for (int j = 0; j < 4; j++)
            #pragma unroll
            for (int e = 0; e < 4; e++) acc[i][j][e] = 0.f;

    for (int kt = 0; kt < K; kt += 32) {
        #pragma unroll
        for (int it = 0; it < 4; it++) {
            int r = lr + it * 32;
            float4 av = *(const float4*)(A + (size_t)(row0 + r) * K + kt + lc4);
            float4 bv = *(const float4*)(B + (size_t)(col0 + r) * K + kt + lc4);
            float4 ah = {f2tf32(av.x), f2tf32(av.y), f2tf32(av.z), f2tf32(av.w)};
            float4 al = {f2tf32(av.x - ah.x), f2tf32(av.y - ah.y), f2tf32(av.z - ah.z), f2tf32(av.w - ah.w)};
            float4 bh = {f2tf32(bv.x), f2tf32(bv.y), f2tf32(bv.z), f2tf32(bv.w)};
            float4 bl = {f2tf32(bv.x - bh.x), f2tf32(bv.y - bh.y), f2tf32(bv.z - bh.z), f2tf32(bv.w - bh.w)};
            *(float4*)&Ah[r * LDT + lc4] = ah;
            *(float4*)&Al[r * LDT + lc4] = al;
            *(float4*)&Bh[r * LDT + lc4] = bh;
            *(float4*)&Bl[r * LDT + lc4] = bl;
        }
        __syncthreads();
        #pragma unroll
        for (int kk = 0; kk < 4; kk++) {
            const int kc = kk * 8;
            unsigned bh_[4][2], bl_[4][2];
            #pragma unroll
            for (int nt = 0; nt < 4; nt++) {
                int nrow = (wn + nt * 8 + g) * LDT + kc + t;
                bh_[nt][0] = __float_as_uint(Bh[nrow]);
                bh_[nt][1] = __float_as_uint(Bh[nrow + 4]);
                bl_[nt][0] = __float_as_uint(Bl[nrow]);
                bl_[nt][1] = __float_as_uint(Bl[nrow + 4]);
            }
            #pragma unroll
            for (int mt = 0; mt < 4; mt++) {
                int r0 = (wm + mt * 16 + g) * LDT + kc + t;
                int r1 = (wm + mt * 16 + g + 8) * LDT + kc + t;
                unsigned ah_[4] = {__float_as_uint(Ah[r0]), __float_as_uint(Ah[r1]),
                                   __float_as_uint(Ah[r0 + 4]), __float_as_uint(Ah[r1 + 4])};
                unsigned al_[4] = {__float_as_uint(Al[r0]), __float_as_uint(Al[r1]),
                                   __float_as_uint(Al[r0 + 4]), __float_as_uint(Al[r1 + 4])};
                #pragma unroll
                for (int nt = 0; nt < 4; nt++) {
                    mma_tf32(acc[mt][nt], ah_, bh_[nt]);
                    mma_tf32(acc[mt][nt], ah_, bl_[nt]);
                    mma_tf32(acc[mt][nt], al_, bh_[nt]);
                }
            }
        }
        __syncthreads();
    }
    #pragma unroll
    for (int mt = 0; mt < 4; mt++) {
        int r = row0 + wm + mt * 16 + g;
        #pragma unroll
        for (int nt = 0; nt < 4; nt++) {
            int c = col0 + wn + nt * 8 + 2 * t;
            float b0 = 0.f, b1 = 0.f;
            if (bias) { b0 = bias[c]; b1 = bias[c + 1]; }
            float2 o0 = {alpha * acc[mt][nt][0] + b0, alpha * acc[mt][nt][1] + b1};
            float2 o1 = {alpha * acc[mt][nt][2] + b0, alpha * acc[mt][nt][3] + b1};
            *(float2*)(C + (size_t)r * N + c) = o0;
            *(float2*)(C + (size_t)(r + 8) * N + c) = o1;
        }
    }
}

// ---------------- Flash attention: QK^T + online softmax + PV, tf32x3 ----------------
// grid (16 qblocks, 16 heads), 256 threads (8 warps x 16 query rows).
// KV tiles of 64 keys. smem: Kh,Kl[64][68], Vh,Vl[64][68] (d-major), Ps[8][16][68].
#define FL_LD 68
#define FL_SMEM ((4 * 64 * FL_LD + 8 * 16 * FL_LD) * 4)
__global__ __launch_bounds__(256, 1) void flash_attn() {
    extern __shared__ float sm[];
    float* Kh = sm;
    float* Kl = Kh + 64 * FL_LD;
    float* Vh = Kl + 64 * FL_LD;
    float* Vl = Vh + 64 * FL_LD;
    float* Ps = Vl + 64 * FL_LD;

    const int tid = threadIdx.x;
    const int lane = tid & 31, warp = tid >> 5;
    const int g = lane >> 2, t = lane & 3;
    const int h = blockIdx.y;
    const int qb = blockIdx.x;
    const float* Qg = g_q + ((size_t)h * NTOK + qb * 128) * HD;
    const float* Kg = g_k + (size_t)h * NTOK * HD;
    const float* Vg = g_v + (size_t)h * NTOK * HD;

    // stage Q (scaled by 1/8) into smem, then build hi/lo A-fragments in registers
    {
        float* Qs = Kh;  // reuse 128*68 region (Kh+Kl)
        int row = tid >> 1, half = tid & 1;
        #pragma unroll
        for (int i = 0; i < 4; i++) {
            float4 v = *(const float4*)(Qg + row * 64 + half * 32 + i * 8);
            float4 w = *(const float4*)(Qg + row * 64 + half * 32 + i * 8 + 4);
            *(float4*)&Qs[row * FL_LD + half * 32 + i * 8] = v;
            *(float4*)&Qs[row * FL_LD + half * 32 + i * 8 + 4] = w;
        }
    }
    __syncthreads();
    unsigned qh[8][4], ql[8][4];
    {
        const float* Qs = Kh;
        int r0 = (warp * 16 + g) * FL_LD, r1 = (warp * 16 + g + 8) * FL_LD;
        #pragma unroll
        for (int kt = 0; kt < 8; kt++) {
            int c = kt * 8 + t;
            float a0 = Qs[r0 + c] * 0.125f;
            float a1 = Qs[r1 + c] * 0.125f;
            float a2 = Qs[r0 + c + 4] * 0.125f;
            float a3 = Qs[r1 + c + 4] * 0.125f;
            float h0 = f2tf32(a0), h1 = f2tf32(a1), h2 = f2tf32(a2), h3 = f2tf32(a3);
            qh[kt][0] = __float_as_uint(h0); qh[kt][1] = __float_as_uint(h1);
            qh[kt][2] = __float_as_uint(h2); qh[kt][3] = __float_as_uint(h3);
            ql[kt][0] = __float_as_uint(f2tf32(a0 - h0));
            ql[kt][1] = __float_as_uint(f2tf32(a1 - h1));
            ql[kt][2] = __float_as_uint(f2tf32(a2 - h2));
            ql[kt][3] = __float_as_uint(f2tf32(a3 - h3));
        }
    }
    __syncthreads();

    float oacc[8][4];
    #pragma unroll
    for (int nt = 0; nt < 8; nt++)
        #pragma unroll
        for (int e = 0; e < 4; e++) oacc[nt][e] = 0.f;
    float m0 = -1e30f, m1 = -1e30f, l0 = 0.f, l1 = 0.f;

    for (int j = 0; j < NTOK / 64; j++) {
        // load K tile (row-major) + V tile (transposed to d-major), hi/lo split
        {
            int row = tid & 63, chunk = tid >> 6;
            const float* kp = Kg + (size_t)(j * 64 + row) * 64 + chunk * 16;
            const float* vp = Vg + (size_t)(j * 64 + row) * 64 + chunk * 16;
            #pragma unroll
            for (int i = 0; i < 4; i++) {
                float4 kv = *(const float4*)(kp + i * 4);
                float4 hh = {f2tf32(kv.x), f2tf32(kv.y), f2tf32(kv.z), f2tf32(kv.w)};
                float4 ll = {f2tf32(kv.x - hh.x), f2tf32(kv.y - hh.y), f2tf32(kv.z - hh.z), f2tf32(kv.w - hh.w)};
                *(float4*)&Kh[row * FL_LD + chunk * 16 + i * 4] = hh;
                *(float4*)&Kl[row * FL_LD + chunk * 16 + i * 4] = ll;
                float4 vv = *(const float4*)(vp + i * 4);
                int d0 = chunk * 16 + i * 4;
                float v0h = f2tf32(vv.x), v1h = f2tf32(vv.y), v2h = f2tf32(vv.z), v3h = f2tf32(vv.w);
                Vh[(d0 + 0) * FL_LD + row] = v0h; Vl[(d0 + 0) * FL_LD + row] = f2tf32(vv.x - v0h);
                Vh[(d0 + 1) * FL_LD + row] = v1h; Vl[(d0 + 1) * FL_LD + row] = f2tf32(vv.y - v1h);
                Vh[(d0 + 2) * FL_LD + row] = v2h; Vl[(d0 + 2) * FL_LD + row] = f2tf32(vv.z - v2h);
                Vh[(d0 + 3) * FL_LD + row] = v3h; Vl[(d0 + 3) * FL_LD + row] = f2tf32(vv.w - v3h);
            }
        }
        __syncthreads();

        // S = Q @ K^T (tf32x3), warp tile 16x64
        float sacc[8][4];
        #pragma unroll
        for (int nt = 0; nt < 8; nt++)
            #pragma unroll
            for (int e = 0; e < 4; e++) sacc[nt][e] = 0.f;
        #pragma unroll
        for (int kt = 0; kt < 8; kt++) {
            int kc = kt * 8 + t;
            #pragma unroll
            for (int nt = 0; nt < 8; nt++) {
                int nr = (nt * 8 + g) * FL_LD + kc;
                unsigned bh_[2] = {__float_as_uint(Kh[nr]), __float_as_uint(Kh[nr + 4])};
                unsigned bl_[2] = {__float_as_uint(Kl[nr]), __float_as_uint(Kl[nr + 4])};
                mma_tf32(sacc[nt], qh[kt], bh_);
                mma_tf32(sacc[nt], qh[kt], bl_);
                mma_tf32(sacc[nt], ql[kt], bh_);
            }
        }

        // online softmax (rows g and g+8)
        float mn0 = -1e30f, mn1 = -1e30f;
        #pragma unroll
        for (int nt = 0; nt < 8; nt++) {
            mn0 = fmaxf(mn0, fmaxf(sacc[nt][0], sacc[nt][1]));
            mn1 = fmaxf(mn1, fmaxf(sacc[nt][2], sacc[nt][3]));
        }
        mn0 = fmaxf(mn0, __shfl_xor_sync(0xffffffffu, mn0, 1));
        mn0 = fmaxf(mn0, __shfl_xor_sync(0xffffffffu, mn0, 2));
        mn1 = fmaxf(mn1, __shfl_xor_sync(0xffffffffu, mn1, 1));
        mn1 = fmaxf(mn1, __shfl_xor_sync(0xffffffffu, mn1, 2));
        float mN0 = fmaxf(m0, mn0), mN1 = fmaxf(m1, mn1);
        float f0 = __expf(m0 - mN0), f1 = __expf(m1 - mN1);
        float s0 = 0.f, s1 = 0.f;
        #pragma unroll
        for (int nt = 0; nt < 8; nt++) {
            sacc[nt][0] = __expf(sacc[nt][0] - mN0);
            sacc[nt][1] = __expf(sacc[nt][1] - mN0);
            sacc[nt][2] = __expf(sacc[nt][2] - mN1);
            sacc[nt][3] = __expf(sacc[nt][3] - mN1);
            s0 += sacc[nt][0] + sacc[nt][1];
            s1 += sacc[nt][2] + sacc[nt][3];
        }
        s0 += __shfl_xor_sync(0xffffffffu, s0, 1);
        s0 += __shfl_xor_sync(0xffffffffu, s0, 2);
        s1 += __shfl_xor_sync(0xffffffffu, s1, 1);
        s1 += __shfl_xor_sync(0xffffffffu, s1, 2);
        l0 = l0 * f0 + s0;
        l1 = l1 * f1 + s1;
        m0 = mN0; m1 = mN1;
        #pragma unroll
        for (int nt = 0; nt < 8; nt++) {
            oacc[nt][0] *= f0; oacc[nt][1] *= f0;
            oacc[nt][2] *= f1; oacc[nt][3] *= f1;
        }

        // P via smem roundtrip (per-warp region), then O += P @ V (tf32x3)
        float* Pw = Ps + warp * 16 * FL_LD;
        #pragma unroll
        for (int nt = 0; nt < 8; nt++) {
            *(float2*)&Pw[g * FL_LD + nt * 8 + 2 * t] = make_float2(sacc[nt][0], sacc[nt][1]);
            *(float2*)&Pw[(g + 8) * FL_LD + nt * 8 + 2 * t] = make_float2(sacc[nt][2], sacc[nt][3]);
        }
        __syncwarp();
        #pragma unroll
        for (int kt = 0; kt < 8; kt++) {
            int kc = kt * 8 + t;
            float a0 = Pw[g * FL_LD + kc];
            float a1 = Pw[(g + 8) * FL_LD + kc];
            float a2 = Pw[g * FL_LD + kc + 4];
            float a3 = Pw[(g + 8) * FL_LD + kc + 4];
            float h0 = f2tf32(a0), h1 = f2tf32(a1), h2 = f2tf32(a2), h3 = f2tf32(a3);
            unsigned ah_[4] = {__float_as_uint(h0), __float_as_uint(h1),
                               __float_as_uint(h2), __float_as_uint(h3)};
            unsigned al_[4] = {__float_as_uint(f2tf32(a0 - h0)), __float_as_uint(f2tf32(a1 - h1)),
                               __float_as_uint(f2tf32(a2 - h2)), __float_as_uint(f2tf32(a3 - h3))};
            #pragma unroll
            for (int nt = 0; nt < 8; nt++) {
                int nr = (nt * 8 + g) * FL_LD + kc;
                unsigned bh_[2] = {__float_as_uint(Vh[nr]), __float_as_uint(Vh[nr + 4])};
                unsigned bl_[2] = {__float_as_uint(Vl[nr]), __float_as_uint(Vl[nr + 4])};
                mma_tf32(oacc[nt], ah_, bh_);
                mma_tf32(oacc[nt], ah_, bl_);
                mma_tf32(oacc[nt], al_, bh_);
            }
        }
        __syncthreads();
    }

    // epilogue: O /= l
    float inv0 = 1.0f / l0, inv1 = 1.0f / l1;
    float* Og = g_oh + ((size_t)h * NTOK + qb * 128 + warp * 16) * HD;
    #pragma unroll
    for (int nt = 0; nt < 8; nt++) {
        int c = nt * 8 + 2 * t;
        *(float2*)(Og + g * HD + c) = make_float2(oacc[nt][0] * inv0, oacc[nt][1] * inv0);
        *(float2*)(Og + (g + 8) * HD + c) = make_float2(oacc[nt][2] * inv1, oacc[nt][3] * inv1);
    }
}

// ---------------- q/k/v transform ----------------
__global__ __launch_bounds__(64) void qkv_transform() {
    int nh = blockIdx.x;
    int n = nh >> 4;
    int h = nh & 15;
    int d = threadIdx.x;
    __shared__ float sq[64], sk[64], sv[64];
    const float* base = g_qkv + (size_t)n * 3072 + h * 64;
    sq[d] = base[d];
    sk[d] = base[1024 + d];
    sv[d] = base[2048 + d];
    __syncthreads();
    int cam = n / NPER;
    int p = n % NPER;
    float px = (float)(p & 31), py = (float)(p >> 5);
    float oq, ok, ov;
    if (d < 32) {
        int gg = d & ~3, i = d & 3;
        const float* P  = g_P + cam * 16;
        const float* Pi = g_Pinv + cam * 16;
        oq = ok = ov = 0.f;
        #pragma unroll
        for (int j = 0; j < 4; j++) {
            oq += Pi[j * 4 + i] * sq[gg + j];
            float pij = P[i * 4 + j];
            ok += pij * sk[gg + j];
            ov += pij * sv[gg + j];
        }
    } else {
        int r = d - 32, pair = r >> 1, part = r & 1;
        float fr = powf(100.f, -(float)(pair & 7) * 0.125f);
        float ang = ((pair < 8) ? px : py) * fr;
        float cc = cosf(ang), ss = sinf(ang);
        int ia = 32 + (pair << 1), ib = ia + 1;
        if (part == 0) { oq = sq[ia] * cc - sq[ib] * ss; ok = sk[ia] * cc - sk[ib] * ss; ov = sv[ia] * cc - sv[ib] * ss; }
        else           { oq = sq[ia] * ss + sq[ib] * cc; ok = sk[ia] * ss + sk[ib] * cc; ov = sv[ia] * ss + sv[ib] * cc; }
    }
    size_t idx = ((size_t)h * NTOK + n) * HD + d;
    g_q[idx] = oq; g_k[idx] = ok; g_v[idx] = ov;
}

// ---------------- output transform ----------------
__global__ __launch_bounds__(64) void out_transform() {
    int nh = blockIdx.x;
    int n = nh >> 4;
    int h = nh & 15;
    int d = threadIdx.x;
    __shared__ float so[64];
    so[d] = g_oh[((size_t)h * NTOK + n) * HD + d];
    __syncthreads();
    int cam = n / NPER;
    int p = n % NPER;
    float px = (float)(p & 31), py = (float)(p >> 5);
    float o;
    if (d < 32) {
        int gg = d & ~3, i = d & 3;
        const float* Pi = g_Pinv + cam * 16;
        o = 0.f;
        #pragma unroll
        for (int j = 0; j < 4; j++) o += Pi[i * 4 + j] * so[gg + j];
    } else {
        int r = d - 32, pair = r >> 1, part = r & 1;
        float fr = powf(100.f, -(float)(pair & 7) * 0.125f);
        float ang = ((pair < 8) ? px : py) * fr;
        float cc = cosf(ang), ss = sinf(ang);
        int ia = 32 + (pair << 1), ib = ia + 1;
        if (part == 0) o =  so[ia] * cc + so[ib] * ss;
        else           o = -so[ia] * ss + so[ib] * cc;
    }
    g_y[(size_t)n * CDIM + h * 64 + d] = o;
}

// ---------------- launch ----------------
extern "C" void kernel_launch(void* const* d_in, const int* in_sizes, int n_in,
                              void* d_out, int out_size) {
    const float* x      = (const float*)d_in[0];
    const float* ext    = (const float*)d_in[1];
    const float* Kmat   = (const float*)d_in[2];
    const float* qkv_w  = (const float*)d_in[3];
    const float* proj_w = (const float*)d_in[4];
    const float* proj_b = (const float*)d_in[5];
    float* out = (float*)d_out;

    const int SM_NT = 4 * 128 * LDT * 4;   // 73728 B
    static bool attr_done = false;
    if (!attr_done) {
        cudaFuncSetAttribute(gemm_nt_tf32, cudaFuncAttributeMaxDynamicSharedMemorySize, SM_NT);
        cudaFuncSetAttribute(flash_attn, cudaFuncAttributeMaxDynamicSharedMemorySize, FL_SMEM);
        attr_done = true;
    }

    void *p_qkv, *p_y;
    cudaGetSymbolAddress(&p_qkv, g_qkv);
    cudaGetSymbolAddress(&p_y, g_y);

    setup_mats<<<1, 32>>>(ext, Kmat);

    // QKV: [2048,3072] = x @ qkv_w^T
    gemm_nt_tf32<<<dim3(3072 / 128, 2048 / 128), 256, SM_NT>>>(
        x, qkv_w, (float*)p_qkv, NTOK, 3072, CDIM, 1.0f, nullptr, 0, 0, 0);

    qkv_transform<<<NTOK * NHEADS, 64>>>();

    // fused attention (QK^T + softmax + PV)
    flash_attn<<<dim3(NTOK / 128, NHEADS), 256, FL_SMEM>>>();

    out_transform<<<NTOK * NHEADS, 64>>>();

    // out = y @ proj_w^T + proj_b
    gemm_nt_tf32<<<dim3(1024 / 128, 2048 / 128), 256, SM_NT>>>(
        (const float*)p_y, proj_w, out, NTOK, CDIM, CDIM, 1.0f, proj_b, 0, 0, 0);
}

// round 5
// speedup vs baseline: 1.7098x; 1.1020x over previous
#include <cuda_runtime.h>
#include <math.h>

#define NTOK 2048
#define CDIM 1024
#define NHEADS 16
#define HD 64
#define NCAM 2
#define NPER 1024
#define LDT 36

// ---------------- scratch ----------------
static __device__ float g_qkv[(size_t)NTOK * 3 * CDIM];
static __device__ float g_q[(size_t)NHEADS * NTOK * HD];
static __device__ float g_k[(size_t)NHEADS * NTOK * HD];
static __device__ float g_v[(size_t)NHEADS * NTOK * HD];
static __device__ float g_oh[(size_t)NHEADS * NTOK * HD];
static __device__ float g_y[(size_t)NTOK * CDIM];
static __device__ float g_P[NCAM * 16];
static __device__ float g_Pinv[NCAM * 16];

// ---------------- helpers ----------------
__device__ __forceinline__ float f2tf32(float x) {
    unsigned u;
    asm("cvt.rna.tf32.f32 %0, %1;" : "=r"(u) : "f"(x));
    return __uint_as_float(u);
}
__device__ __forceinline__ void mma_tf32(float* d, const unsigned* a, const unsigned* b) {
    asm volatile(
        "mma.sync.aligned.m16n8k8.row.col.f32.tf32.tf32.f32 "
        "{%0,%1,%2,%3}, {%4,%5,%6,%7}, {%8,%9}, {%0,%1,%2,%3};\n"
        : "+f"(d[0]), "+f"(d[1]), "+f"(d[2]), "+f"(d[3])
        : "r"(a[0]), "r"(a[1]), "r"(a[2]), "r"(a[3]), "r"(b[0]), "r"(b[1]));
}

// ---------------- camera matrices ----------------
__global__ void setup_mats(const float* __restrict__ ext, const float* __restrict__ Ks) {
    int c = threadIdx.x;
    if (c >= NCAM) return;
    const float sx = 2.0f / 448.0f, sy = 2.0f / 448.0f;
    float fx = Ks[c * 9 + 0], cx = Ks[c * 9 + 2];
    float fy = Ks[c * 9 + 4], cy = Ks[c * 9 + 5];
    float Kn[4][4] = {};
    Kn[0][0] = fx * sx; Kn[0][2] = cx * sx - 1.0f;
    Kn[1][1] = fy * sy; Kn[1][2] = cy * sy - 1.0f;
    Kn[2][2] = 1.0f;    Kn[3][3] = 1.0f;
    float P[4][4];
    for (int i = 0; i < 4; i++)
        for (int j = 0; j < 4; j++) {
            float s = 0.f;
            for (int k = 0; k < 4; k++) s += Kn[i][k] * ext[c * 16 + k * 4 + j];
            P[i][j] = s;
            g_P[c * 16 + i * 4 + j] = s;
        }
    float M[4][8];
    for (int i = 0; i < 4; i++)
        for (int j = 0; j < 4; j++) { M[i][j] = P[i][j]; M[i][4 + j] = (i == j) ? 1.f : 0.f; }
    for (int col = 0; col < 4; col++) {
        int piv = col;
        for (int r = col + 1; r < 4; r++)
            if (fabsf(M[r][col]) > fabsf(M[piv][col])) piv = r;
        if (piv != col)
            for (int j = 0; j < 8; j++) { float t = M[col][j]; M[col][j] = M[piv][j]; M[piv][j] = t; }
        float inv = 1.0f / M[col][col];
        for (int j = 0; j < 8; j++) M[col][j] *= inv;
        for (int r = 0; r < 4; r++) if (r != col) {
            float f = M[r][col];
            for (int j = 0; j < 8; j++) M[r][j] -= f * M[col][j];
        }
    }
    for (int i = 0; i < 4; i++)
        for (int j = 0; j < 4; j++) g_Pinv[c * 16 + i * 4 + j] = M[i][4 + j];
}

// ---------------- TF32x3 GEMM NT, double-buffered ----------------
#define GSTG (4 * 128 * LDT)
#define SM_NT (2 * GSTG * 4)
__global__ __launch_bounds__(256) void gemm_nt_tf32(
    const float* __restrict__ A, const float* __restrict__ B, float* __restrict__ C,
    int M, int N, int K, float alpha, const float* __restrict__ bias,
    size_t sA, size_t sB, size_t sC)
{
    A += (size_t)blockIdx.z * sA;
    B += (size_t)blockIdx.z * sB;
    C += (size_t)blockIdx.z * sC;
    extern __shared__ float sm[];
    const int tid = threadIdx.x;
    const int lane = tid & 31, warp = tid >> 5;
    const int g = lane >> 2, t = lane & 3;
    const int wm = (warp >> 2) * 64, wn = (warp & 3) * 32;
    const int row0 = blockIdx.y * 128;
    const int col0 = blockIdx.x * 128;
    const int lr = tid >> 3;
    const int lc4 = (tid & 7) * 4;
    float acc[4][4][4];
    #pragma unroll
    for (int i = 0; i < 4; i++)
        #pragma unroll
        for (int j = 0; j < 4; j++)
            #pragma unroll
            for (int e = 0; e < 4; e++) acc[i][j][e] = 0.f;

    float4 avr[4], bvr[4];
    #pragma unroll
    for (int it = 0; it < 4; it++) {
        int r = lr + it * 32;
        avr[it] = *(const float4*)(A + (size_t)(row0 + r) * K + lc4);
        bvr[it] = *(const float4*)(B + (size_t)(col0 + r) * K + lc4);
    }
    {
        float* Ah = sm;
        float* Al = Ah + 128 * LDT;
        float* Bh = Al + 128 * LDT;
        float* Bl = Bh + 128 * LDT;
        #pragma unroll
        for (int it = 0; it < 4; it++) {
            int r = lr + it * 32;
            float4 av = avr[it], bv = bvr[it];
            float4 ah = {f2tf32(av.x), f2tf32(av.y), f2tf32(av.z), f2tf32(av.w)};
            float4 al = {f2tf32(av.x - ah.x), f2tf32(av.y - ah.y), f2tf32(av.z - ah.z), f2tf32(av.w - ah.w)};
            float4 bh = {f2tf32(bv.x), f2tf32(bv.y), f2tf32(bv.z), f2tf32(bv.w)};
            float4 bl = {f2tf32(bv.x - bh.x), f2tf32(bv.y - bh.y), f2tf32(bv.z - bh.z), f2tf32(bv.w - bh.w)};
            *(float4*)&Ah[r * LDT + lc4] = ah;
            *(float4*)&Al[r * LDT + lc4] = al;
            *(float4*)&Bh[r * LDT + lc4] = bh;
            *(float4*)&Bl[r * LDT + lc4] = bl;
        }
    }
    __syncthreads();

    int buf = 0;
    for (int kt = 0; kt < K; kt += 32) {
        bool more = (kt + 32 < K);
        if (more) {
            #pragma unroll
            for (int it = 0; it < 4; it++) {
                int r = lr + it * 32;
                avr[it] = *(const float4*)(A + (size_t)(row0 + r) * K + kt + 32 + lc4);
                bvr[it] = *(const float4*)(B + (size_t)(col0 + r) * K + kt + 32 + lc4);
            }
        }
        const float* Ah = sm + buf * GSTG;
        const float* Al = Ah + 128 * LDT;
        const float* Bh = Al + 128 * LDT;
        const float* Bl = Bh + 128 * LDT;
        #pragma unroll
        for (int kk = 0; kk < 4; kk++) {
            const int kc = kk * 8;
            unsigned bh_[4][2], bl_[4][2];
            #pragma unroll
            for (int nt = 0; nt < 4; nt++) {
                int nrow = (wn + nt * 8 + g) * LDT + kc + t;
                bh_[nt][0] = __float_as_uint(Bh[nrow]);
                bh_[nt][1] = __float_as_uint(Bh[nrow + 4]);
                bl_[nt][0] = __float_as_uint(Bl[nrow]);
                bl_[nt][1] = __float_as_uint(Bl[nrow + 4]);
            }
            #pragma unroll
            for (int mt = 0; mt < 4; mt++) {
                int r0 = (wm + mt * 16 + g) * LDT + kc + t;
                int r1 = (wm + mt * 16 + g + 8) * LDT + kc + t;
                unsigned ah_[4] = {__float_as_uint(Ah[r0]), __float_as_uint(Ah[r1]),
                                   __float_as_uint(Ah[r0 + 4]), __float_as_uint(Ah[r1 + 4])};
                unsigned al_[4] = {__float_as_uint(Al[r0]), __float_as_uint(Al[r1]),
                                   __float_as_uint(Al[r0 + 4]), __float_as_uint(Al[r1 + 4])};
                #pragma unroll
                for (int nt = 0; nt < 4; nt++) {
                    mma_tf32(acc[mt][nt], ah_, bh_[nt]);
                    mma_tf32(acc[mt][nt], ah_, bl_[nt]);
                    mma_tf32(acc[mt][nt], al_, bh_[nt]);
                }
            }
        }
        if (more) {
            float* Ah2 = sm + (buf ^ 1) * GSTG;
            float* Al2 = Ah2 + 128 * LDT;
            float* Bh2 = Al2 + 128 * LDT;
            float* Bl2 = Bh2 + 128 * LDT;
            #pragma unroll
            for (int it = 0; it < 4; it++) {
                int r = lr + it * 32;
                float4 av = avr[it], bv = bvr[it];
                float4 ah = {f2tf32(av.x), f2tf32(av.y), f2tf32(av.z), f2tf32(av.w)};
                float4 al = {f2tf32(av.x - ah.x), f2tf32(av.y - ah.y), f2tf32(av.z - ah.z), f2tf32(av.w - ah.w)};
                float4 bh = {f2tf32(bv.x), f2tf32(bv.y), f2tf32(bv.z), f2tf32(bv.w)};
                float4 bl = {f2tf32(bv.x - bh.x), f2tf32(bv.y - bh.y), f2tf32(bv.z - bh.z), f2tf32(bv.w - bh.w)};
                *(float4*)&Ah2[r * LDT + lc4] = ah;
                *(float4*)&Al2[r * LDT + lc4] = al;
                *(float4*)&Bh2[r * LDT + lc4] = bh;
                *(float4*)&Bl2[r * LDT + lc4] = bl;
            }
        }
        __syncthreads();
        buf ^= 1;
    }
    #pragma unroll
    for (int mt = 0; mt < 4; mt++) {
        int r = row0 + wm + mt * 16 + g;
        #pragma unroll
        for (int nt = 0; nt < 4; nt++) {
            int c = col0 + wn + nt * 8 + 2 * t;
            float b0 = 0.f, b1 = 0.f;
            if (bias) { b0 = bias[c]; b1 = bias[c + 1]; }
            float2 o0 = {alpha * acc[mt][nt][0] + b0, alpha * acc[mt][nt][1] + b1};
            float2 o1 = {alpha * acc[mt][nt][2] + b0, alpha * acc[mt][nt][3] + b1};
            *(float2*)(C + (size_t)r * N + c) = o0;
            *(float2*)(C + (size_t)(r + 8) * N + c) = o1;
        }
    }
}

// ---------------- Flash attention, double-buffered KV ----------------
// smem: Ps/Qs [128][68], then 2 stages x {Kh,Kl,Vh,Vl}[64][68]
#define FL_LD 68
#define FL_STG (4 * 64 * FL_LD)
#define FL_SMEM ((128 * FL_LD + 2 * FL_STG) * 4)
#define NKVT (NTOK / 64)
__global__ __launch_bounds__(256, 1) void flash_attn() {
    extern __shared__ float sm[];
    float* Ps = sm;                       // 128 x FL_LD (also Q staging)
    float* KVbase = sm + 128 * FL_LD;

    const int tid = threadIdx.x;
    const int lane = tid & 31, warp = tid >> 5;
    const int g = lane >> 2, t = lane & 3;
    const int h = blockIdx.y;
    const int qb = blockIdx.x;
    const float* Qg = g_q + ((size_t)h * NTOK + qb * 128) * HD;
    const float* Kg = g_k + (size_t)h * NTOK * HD;
    const float* Vg = g_v + (size_t)h * NTOK * HD;

    const int ldrow = tid & 63, ldchunk = tid >> 6;   // KV tile load mapping

    // stage Q into Ps region, extract scaled hi/lo A-fragments
    {
        int row = tid >> 1, half = tid & 1;
        #pragma unroll
        for (int i = 0; i < 4; i++) {
            float4 v = *(const float4*)(Qg + row * 64 + half * 32 + i * 8);
            float4 w = *(const float4*)(Qg + row * 64 + half * 32 + i * 8 + 4);
            *(float4*)&Ps[row * FL_LD + half * 32 + i * 8] = v;
            *(float4*)&Ps[row * FL_LD + half * 32 + i * 8 + 4] = w;
        }
    }
    __syncthreads();
    unsigned qh[8][4], ql[8][4];
    {
        int r0 = (warp * 16 + g) * FL_LD, r1 = (warp * 16 + g + 8) * FL_LD;
        #pragma unroll
        for (int kt = 0; kt < 8; kt++) {
            int c = kt * 8 + t;
            float a0 = Ps[r0 + c] * 0.125f;
            float a1 = Ps[r1 + c] * 0.125f;
            float a2 = Ps[r0 + c + 4] * 0.125f;
            float a3 = Ps[r1 + c + 4] * 0.125f;
            float h0 = f2tf32(a0), h1 = f2tf32(a1), h2 = f2tf32(a2), h3 = f2tf32(a3);
            qh[kt][0] = __float_as_uint(h0); qh[kt][1] = __float_as_uint(h1);
            qh[kt][2] = __float_as_uint(h2); qh[kt][3] = __float_as_uint(h3);
            ql[kt][0] = __float_as_uint(f2tf32(a0 - h0));
            ql[kt][1] = __float_as_uint(f2tf32(a1 - h1));
            ql[kt][2] = __float_as_uint(f2tf32(a2 - h2));
            ql[kt][3] = __float_as_uint(f2tf32(a3 - h3));
        }
    }

    float4 kreg[4], vreg[4];
    // prologue: load tile 0, store to stage 0
    #pragma unroll
    for (int i = 0; i < 4; i++) {
        kreg[i] = *(const float4*)(Kg + (size_t)ldrow * 64 + ldchunk * 16 + i * 4);
        vreg[i] = *(const float4*)(Vg + (size_t)ldrow * 64 + ldchunk * 16 + i * 4);
    }
    __syncthreads();   // Q staging reads done before Ps reused / stage stores begin
    {
        float* Kh = KVbase;
        float* Kl = Kh + 64 * FL_LD;
        float* Vh = Kl + 64 * FL_LD;
        float* Vl = Vh + 64 * FL_LD;
        #pragma unroll
        for (int i = 0; i < 4; i++) {
            float4 kv = kreg[i];
            float4 hh = {f2tf32(kv.x), f2tf32(kv.y), f2tf32(kv.z), f2tf32(kv.w)};
            float4 ll = {f2tf32(kv.x - hh.x), f2tf32(kv.y - hh.y), f2tf32(kv.z - hh.z), f2tf32(kv.w - hh.w)};
            *(float4*)&Kh[ldrow * FL_LD + ldchunk * 16 + i * 4] = hh;
            *(float4*)&Kl[ldrow * FL_LD + ldchunk * 16 + i * 4] = ll;
            float4 vv = vreg[i];
            int d0 = ldchunk * 16 + i * 4;
            float v0h = f2tf32(vv.x), v1h = f2tf32(vv.y), v2h = f2tf32(vv.z), v3h = f2tf32(vv.w);
            Vh[(d0 + 0) * FL_LD + ldrow] = v0h; Vl[(d0 + 0) * FL_LD + ldrow] = f2tf32(vv.x - v0h);
            Vh[(d0 + 1) * FL_LD + ldrow] = v1h; Vl[(d0 + 1) * FL_LD + ldrow] = f2tf32(vv.y - v1h);
            Vh[(d0 + 2) * FL_LD + ldrow] = v2h; Vl[(d0 + 2) * FL_LD + ldrow] = f2tf32(vv.z - v2h);
            Vh[(d0 + 3) * FL_LD + ldrow] = v3h; Vl[(d0 + 3) * FL_LD + ldrow] = f2tf32(vv.w - v3h);
        }
    }
    __syncthreads();

    float oacc[8][4];
    #pragma unroll
    for (int nt = 0; nt < 8; nt++)
        #pragma unroll
        for (int e = 0; e < 4; e++) oacc[nt][e] = 0.f;
    float m0 = -1e30f, m1 = -1e30f, l0 = 0.f, l1 = 0.f;

    int buf = 0;
    for (int j = 0; j < NKVT; j++) {
        bool more = (j + 1 < NKVT);
        if (more) {
            const float* kp = Kg + (size_t)((j + 1) * 64 + ldrow) * 64 + ldchunk * 16;
            const float* vp = Vg + (size_t)((j + 1) * 64 + ldrow) * 64 + ldchunk * 16;
            #pragma unroll
            for (int i = 0; i < 4; i++) {
                kreg[i] = *(const float4*)(kp + i * 4);
                vreg[i] = *(const float4*)(vp + i * 4);
            }
        }
        const float* Kh = KVbase + buf * FL_STG;
        const float* Kl = Kh + 64 * FL_LD;
        const float* Vh = Kl + 64 * FL_LD;
        const float* Vl = Vh + 64 * FL_LD;

        // S = Q @ K^T
        float sacc[8][4];
        #pragma unroll
        for (int nt = 0; nt < 8; nt++)
            #pragma unroll
            for (int e = 0; e < 4; e++) sacc[nt][e] = 0.f;
        #pragma unroll
        for (int kt = 0; kt < 8; kt++) {
            int kc = kt * 8 + t;
            #pragma unroll
            for (int nt = 0; nt < 8; nt++) {
                int nr = (nt * 8 + g) * FL_LD + kc;
                unsigned bh_[2] = {__float_as_uint(Kh[nr]), __float_as_uint(Kh[nr + 4])};
                unsigned bl_[2] = {__float_as_uint(Kl[nr]), __float_as_uint(Kl[nr + 4])};
                mma_tf32(sacc[nt], qh[kt], bh_);
                mma_tf32(sacc[nt], qh[kt], bl_);
                mma_tf32(sacc[nt], ql[kt], bh_);
            }
        }

        // online softmax
        float mn0 = -1e30f, mn1 = -1e30f;
        #pragma unroll
        for (int nt = 0; nt < 8; nt++) {
            mn0 = fmaxf(mn0, fmaxf(sacc[nt][0], sacc[nt][1]));
            mn1 = fmaxf(mn1, fmaxf(sacc[nt][2], sacc[nt][3]));
        }
        mn0 = fmaxf(mn0, __shfl_xor_sync(0xffffffffu, mn0, 1));
        mn0 = fmaxf(mn0, __shfl_xor_sync(0xffffffffu, mn0, 2));
        mn1 = fmaxf(mn1, __shfl_xor_sync(0xffffffffu, mn1, 1));
        mn1 = fmaxf(mn1, __shfl_xor_sync(0xffffffffu, mn1, 2));
        float mN0 = fmaxf(m0, mn0), mN1 = fmaxf(m1, mn1);
        float f0 = __expf(m0 - mN0), f1 = __expf(m1 - mN1);
        float s0 = 0.f, s1 = 0.f;
        #pragma unroll
        for (int nt = 0; nt < 8; nt++) {
            sacc[nt][0] = __expf(sacc[nt][0] - mN0);
            sacc[nt][1] = __expf(sacc[nt][1] - mN0);
            sacc[nt][2] = __expf(sacc[nt][2] - mN1);
            sacc[nt][3] = __expf(sacc[nt][3] - mN1);
            s0 += sacc[nt][0] + sacc[nt][1];
            s1 += sacc[nt][2] + sacc[nt][3];
        }
        s0 += __shfl_xor_sync(0xffffffffu, s0, 1);
        s0 += __shfl_xor_sync(0xffffffffu, s0, 2);
        s1 += __shfl_xor_sync(0xffffffffu, s1, 1);
        s1 += __shfl_xor_sync(0xffffffffu, s1, 2);
        l0 = l0 * f0 + s0;
        l1 = l1 * f1 + s1;
        m0 = mN0; m1 = mN1;
        #pragma unroll
        for (int nt = 0; nt < 8; nt++) {
            oacc[nt][0] *= f0; oacc[nt][1] *= f0;
            oacc[nt][2] *= f1; oacc[nt][3] *= f1;
        }

        // P via per-warp smem pad, then O += P @ V
        float* Pw = Ps + warp * 16 * FL_LD;
        #pragma unroll
        for (int nt = 0; nt < 8; nt++) {
            *(float2*)&Pw[g * FL_LD + nt * 8 + 2 * t] = make_float2(sacc[nt][0], sacc[nt][1]);
            *(float2*)&Pw[(g + 8) * FL_LD + nt * 8 + 2 * t] = make_float2(sacc[nt][2], sacc[nt][3]);
        }
        __syncwarp();
        #pragma unroll
        for (int kt = 0; kt < 8; kt++) {
            int kc = kt * 8 + t;
            float a0 = Pw[g * FL_LD + kc];
            float a1 = Pw[(g + 8) * FL_LD + kc];
            float a2 = Pw[g * FL_LD + kc + 4];
            float a3 = Pw[(g + 8) * FL_LD + kc + 4];
            float h0 = f2tf32(a0), h1 = f2tf32(a1), h2 = f2tf32(a2), h3 = f2tf32(a3);
            unsigned ah_[4] = {__float_as_uint(h0), __float_as_uint(h1),
                               __float_as_uint(h2), __float_as_uint(h3)};
            unsigned al_[4] = {__float_as_uint(f2tf32(a0 - h0)), __float_as_uint(f2tf32(a1 - h1)),
                               __float_as_uint(f2tf32(a2 - h2)), __float_as_uint(f2tf32(a3 - h3))};
            #pragma unroll
            for (int nt = 0; nt < 8; nt++) {
                int nr = (nt * 8 + g) * FL_LD + kc;
                unsigned bh_[2] = {__float_as_uint(Vh[nr]), __float_as_uint(Vh[nr + 4])};
                unsigned bl_[2] = {__float_as_uint(Vl[nr]), __float_as_uint(Vl[nr + 4])};
                mma_tf32(oacc[nt], ah_, bh_);
                mma_tf32(oacc[nt], ah_, bl_);
                mma_tf32(oacc[nt], al_, bh_);
            }
        }

        if (more) {
            float* Kh2 = KVbase + (buf ^ 1) * FL_STG;
            float* Kl2 = Kh2 + 64 * FL_LD;
            float* Vh2 = Kl2 + 64 * FL_LD;
            float* Vl2 = Vh2 + 64 * FL_LD;
            #pragma unroll
            for (int i = 0; i < 4; i++) {
                float4 kv = kreg[i];
                float4 hh = {f2tf32(kv.x), f2tf32(kv.y), f2tf32(kv.z), f2tf32(kv.w)};
                float4 ll = {f2tf32(kv.x - hh.x), f2tf32(kv.y - hh.y), f2tf32(kv.z - hh.z), f2tf32(kv.w - hh.w)};
                *(float4*)&Kh2[ldrow * FL_LD + ldchunk * 16 + i * 4] = hh;
                *(float4*)&Kl2[ldrow * FL_LD + ldchunk * 16 + i * 4] = ll;
                float4 vv = vreg[i];
                int d0 = ldchunk * 16 + i * 4;
                float v0h = f2tf32(vv.x), v1h = f2tf32(vv.y), v2h = f2tf32(vv.z), v3h = f2tf32(vv.w);
                Vh2[(d0 + 0) * FL_LD + ldrow] = v0h; Vl2[(d0 + 0) * FL_LD + ldrow] = f2tf32(vv.x - v0h);
                Vh2[(d0 + 1) * FL_LD + ldrow] = v1h; Vl2[(d0 + 1) * FL_LD + ldrow] = f2tf32(vv.y - v1h);
                Vh2[(d0 + 2) * FL_LD + ldrow] = v2h; Vl2[(d0 + 2) * FL_LD + ldrow] = f2tf32(vv.z - v2h);
                Vh2[(d0 + 3) * FL_LD + ldrow] = v3h; Vl2[(d0 + 3) * FL_LD + ldrow] = f2tf32(vv.w - v3h);
            }
        }
        __syncthreads();
        buf ^= 1;
    }

    float inv0 = 1.0f / l0, inv1 = 1.0f / l1;
    float* Og = g_oh + ((size_t)h * NTOK + qb * 128 + warp * 16) * HD;
    #pragma unroll
    for (int nt = 0; nt < 8; nt++) {
        int c = nt * 8 + 2 * t;
        *(float2*)(Og + g * HD + c) = make_float2(oacc[nt][0] * inv0, oacc[nt][1] * inv0);
        *(float2*)(Og + (g + 8) * HD + c) = make_float2(oacc[nt][2] * inv1, oacc[nt][3] * inv1);
    }
}

// ---------------- q/k/v transform ----------------
__global__ __launch_bounds__(64) void qkv_transform() {
    int nh = blockIdx.x;
    int n = nh >> 4;
    int h = nh & 15;
    int d = threadIdx.x;
    __shared__ float sq[64], sk[64], sv[64];
    const float* base = g_qkv + (size_t)n * 3072 + h * 64;
    sq[d] = base[d];
    sk[d] = base[1024 + d];
    sv[d] = base[2048 + d];
    __syncthreads();
    int cam = n / NPER;
    int p = n % NPER;
    float px = (float)(p & 31), py = (float)(p >> 5);
    float oq, ok, ov;
    if (d < 32) {
        int gg = d & ~3, i = d & 3;
        const float* P  = g_P + cam * 16;
        const float* Pi = g_Pinv + cam * 16;
        oq = ok = ov = 0.f;
        #pragma unroll
        for (int j = 0; j < 4; j++) {
            oq += Pi[j * 4 + i] * sq[gg + j];
            float pij = P[i * 4 + j];
            ok += pij * sk[gg + j];
            ov += pij * sv[gg + j];
        }
    } else {
        int r = d - 32, pair = r >> 1, part = r & 1;
        float fr = powf(100.f, -(float)(pair & 7) * 0.125f);
        float ang = ((pair < 8) ? px : py) * fr;
        float cc = cosf(ang), ss = sinf(ang);
        int ia = 32 + (pair << 1), ib = ia + 1;
        if (part == 0) { oq = sq[ia] * cc - sq[ib] * ss; ok = sk[ia] * cc - sk[ib] * ss; ov = sv[ia] * cc - sv[ib] * ss; }
        else           { oq = sq[ia] * ss + sq[ib] * cc; ok = sk[ia] * ss + sk[ib] * cc; ov = sv[ia] * ss + sv[ib] * cc; }
    }
    size_t idx = ((size_t)h * NTOK + n) * HD + d;
    g_q[idx] = oq; g_k[idx] = ok; g_v[idx] = ov;
}

// ---------------- output transform ----------------
__global__ __launch_bounds__(64) void out_transform() {
    int nh = blockIdx.x;
    int n = nh >> 4;
    int h = nh & 15;
    int d = threadIdx.x;
    __shared__ float so[64];
    so[d] = g_oh[((size_t)h * NTOK + n) * HD + d];
    __syncthreads();
    int cam = n / NPER;
    int p = n % NPER;
    float px = (float)(p & 31), py = (float)(p >> 5);
    float o;
    if (d < 32) {
        int gg = d & ~3, i = d & 3;
        const float* Pi = g_Pinv + cam * 16;
        o = 0.f;
        #pragma unroll
        for (int j = 0; j < 4; j++) o += Pi[i * 4 + j] * so[gg + j];
    } else {
        int r = d - 32, pair = r >> 1, part = r & 1;
        float fr = powf(100.f, -(float)(pair & 7) * 0.125f);
        float ang = ((pair < 8) ? px : py) * fr;
        float cc = cosf(ang), ss = sinf(ang);
        int ia = 32 + (pair << 1), ib = ia + 1;
        if (part == 0) o =  so[ia] * cc + so[ib] * ss;
        else           o = -so[ia] * ss + so[ib] * cc;
    }
    g_y[(size_t)n * CDIM + h * 64 + d] = o;
}

// ---------------- launch ----------------
extern "C" void kernel_launch(void* const* d_in, const int* in_sizes, int n_in,
                              void* d_out, int out_size) {
    const float* x      = (const float*)d_in[0];
    const float* ext    = (const float*)d_in[1];
    const float* Kmat   = (const float*)d_in[2];
    const float* qkv_w  = (const float*)d_in[3];
    const float* proj_w = (const float*)d_in[4];
    const float* proj_b = (const float*)d_in[5];
    float* out = (float*)d_out;

    static bool attr_done = false;
    if (!attr_done) {
        cudaFuncSetAttribute(gemm_nt_tf32, cudaFuncAttributeMaxDynamicSharedMemorySize, SM_NT);
        cudaFuncSetAttribute(flash_attn, cudaFuncAttributeMaxDynamicSharedMemorySize, FL_SMEM);
        attr_done = true;
    }

    void *p_qkv, *p_y;
    cudaGetSymbolAddress(&p_qkv, g_qkv);
    cudaGetSymbolAddress(&p_y, g_y);

    setup_mats<<<1, 32>>>(ext, Kmat);

    // QKV: [2048,3072] = x @ qkv_w^T
    gemm_nt_tf32<<<dim3(3072 / 128, 2048 / 128), 256, SM_NT>>>(
        x, qkv_w, (float*)p_qkv, NTOK, 3072, CDIM, 1.0f, nullptr, 0, 0, 0);

    qkv_transform<<<NTOK * NHEADS, 64>>>();

    // fused attention
    flash_attn<<<dim3(NTOK / 128, NHEADS), 256, FL_SMEM>>>();

    out_transform<<<NTOK * NHEADS, 64>>>();

    // out = y @ proj_w^T + proj_b
    gemm_nt_tf32<<<dim3(1024 / 128, 2048 / 128), 256, SM_NT>>>(
        (const float*)p_y, proj_w, out, NTOK, CDIM, CDIM, 1.0f, proj_b, 0, 0, 0);
}